// round 4
// baseline (speedup 1.0000x reference)
#include <cuda_runtime.h>
#include <math.h>
#include <stdint.h>

#define NN 100000
#define EE 800000
#define FD 128   // H * C
#define KD 64    // input/output dim of each GEMM
#define EDD 32   // edge attr dim
#define HH 2     // heads

// ---------------- scratch (device globals) -----------------------------------
__device__ int   g_degi[NN];       // src degree (for degree_norm)
__device__ int   g_dcnt[NN];       // dst degree (for CSR)
__device__ int   g_cur[NN];        // CSR fill cursor
__device__ int   g_doff[NN + 1];   // CSR row offsets
__device__ int   g_srcs[EE];       // src node id, CSR order
__device__ int   g_epos[EE];       // edge -> CSR slot
__device__ float g_dn1[NN];
__device__ float g_dn2[NN];
__device__ float g_Wq[FD * KD];
__device__ float g_v1[HH * EDD];
__device__ float g_v2[HH * EDD];
__device__ float g_ae1[EE * HH];   // a_edge layer 1, CSR order
__device__ float g_ae2[EE * HH];   // a_edge layer 2, CSR order
__device__ float g_h[NN * FD];     // 51.2 MB
__device__ float g_asrc[NN * HH];
__device__ float g_adst[NN * HH];
__device__ float g_x2[NN * KD];    // 25.6 MB
__device__ float g_wscale[1];
__device__ int   g_imax[1];

// ---------------- init / degree / CSR ----------------------------------------
__global__ void k_zero() {
    int i = blockIdx.x * blockDim.x + threadIdx.x;
    if (i < NN) { g_degi[i] = 0; g_dcnt[i] = 0; g_cur[i] = 0; }
}

__global__ void k_deg(const int* __restrict__ src, const int* __restrict__ dst) {
    int e = blockIdx.x * blockDim.x + threadIdx.x;
    if (e < EE) {
        atomicAdd(&g_degi[src[e]], 1);
        atomicAdd(&g_dcnt[dst[e]], 1);
    }
}

__global__ void k_dnorm(const float* __restrict__ a1, const float* __restrict__ a2) {
    int n = blockIdx.x * blockDim.x + threadIdx.x;
    if (n < NN) {
        float d = (float)(g_degi[n] + 1);
        g_dn1[n] = powf(d, -a1[0]);
        g_dn2[n] = powf(d, -a2[0]);
    }
}

// single-block exclusive scan of g_dcnt -> g_doff
__global__ void k_scan() {
    __shared__ int part[1024];
    int t = threadIdx.x;
    const int CH = (NN + 1023) / 1024;
    int beg = t * CH;
    int end = min(beg + CH, NN);
    int s = 0;
    for (int i = beg; i < end; i++) s += g_dcnt[i];
    part[t] = s;
    __syncthreads();
    for (int o = 1; o < 1024; o <<= 1) {
        int v = (t >= o) ? part[t - o] : 0;
        __syncthreads();
        part[t] += v;
        __syncthreads();
    }
    int run = t ? part[t - 1] : 0;
    for (int i = beg; i < end; i++) { g_doff[i] = run; run += g_dcnt[i]; }
    if (t == 1023) g_doff[NN] = run;
}

__global__ void k_fill(const int* __restrict__ src, const int* __restrict__ dst) {
    int e = blockIdx.x * blockDim.x + threadIdx.x;
    if (e >= EE) return;
    int d = dst[e];
    int pos = g_doff[d] + atomicAdd(&g_cur[d], 1);
    g_srcs[pos] = src[e];
    g_epos[e] = pos;
}

// ---------------- fake-quant of W -------------------------------------------
__global__ void k_maxabsW(const float* __restrict__ w) {
    __shared__ float sm[256];
    float m = 0.f;
    for (int i = threadIdx.x; i < FD * KD; i += 256) m = fmaxf(m, fabsf(w[i]));
    sm[threadIdx.x] = m;
    __syncthreads();
    for (int s = 128; s > 0; s >>= 1) {
        if (threadIdx.x < s) sm[threadIdx.x] = fmaxf(sm[threadIdx.x], sm[threadIdx.x + s]);
        __syncthreads();
    }
    if (threadIdx.x == 0) {
        g_wscale[0] = fmaxf(sm[0], 1e-8f) / 127.0f;
        g_imax[0] = 0;                 // reset output-quant max for this layer
    }
}

__global__ void k_quantW(const float* __restrict__ w) {
    int i = blockIdx.x * blockDim.x + threadIdx.x;
    if (i < FD * KD) {
        float s = g_wscale[0];
        float q = rintf(w[i] / s);
        q = fminf(fmaxf(q, -128.f), 127.f);
        g_Wq[i] = q * s;
    }
}

// v[h,d] = sum_c att_edge[h,c] * We[(h*64+c), d]  -- both layers, one launch.
// 256 threads: 64 outputs x 4-way split of the c loop, smem reduce.
__global__ void k_vedge(const float* __restrict__ We1, const float* __restrict__ ae1,
                        const float* __restrict__ We2, const float* __restrict__ ae2) {
    __shared__ float r1[64][4];
    __shared__ float r2[64][4];
    int t = threadIdx.x;
    int i = t >> 2;       // output index 0..63
    int j = t & 3;        // c-split
    int h = i / EDD, d = i % EDD;
    float s1 = 0.f, s2 = 0.f;
    for (int c = j * 16; c < j * 16 + 16; c++) {
        s1 += ae1[h * 64 + c] * We1[(h * 64 + c) * EDD + d];
        s2 += ae2[h * 64 + c] * We2[(h * 64 + c) * EDD + d];
    }
    r1[i][j] = s1; r2[i][j] = s2;
    __syncthreads();
    if (j == 0) {
        g_v1[i] = r1[i][0] + r1[i][1] + r1[i][2] + r1[i][3];
        g_v2[i] = r2[i][0] + r2[i][1] + r2[i][2] + r2[i][3];
    }
}

// one pass over edge_attr computing a_edge for BOTH layers, stored in CSR order
__global__ void k_edgepre(const float* __restrict__ ea) {
    __shared__ float sv1[HH * EDD];
    __shared__ float sv2[HH * EDD];
    if (threadIdx.x < HH * EDD) { sv1[threadIdx.x] = g_v1[threadIdx.x]; sv2[threadIdx.x] = g_v2[threadIdx.x]; }
    __syncthreads();
    int e = blockIdx.x * blockDim.x + threadIdx.x;
    if (e >= EE) return;
    const float4* p = (const float4*)(ea + (size_t)e * EDD);
    float a0 = 0.f, a1 = 0.f, b0 = 0.f, b1 = 0.f;
#pragma unroll
    for (int i = 0; i < 8; i++) {
        float4 q = p[i];
        a0 += q.x * sv1[i*4] + q.y * sv1[i*4+1] + q.z * sv1[i*4+2] + q.w * sv1[i*4+3];
        a1 += q.x * sv1[32+i*4] + q.y * sv1[32+i*4+1] + q.z * sv1[32+i*4+2] + q.w * sv1[32+i*4+3];
        b0 += q.x * sv2[i*4] + q.y * sv2[i*4+1] + q.z * sv2[i*4+2] + q.w * sv2[i*4+3];
        b1 += q.x * sv2[32+i*4] + q.y * sv2[32+i*4+1] + q.z * sv2[32+i*4+2] + q.w * sv2[32+i*4+3];
    }
    int pos = g_epos[e];
    ((float2*)g_ae1)[pos] = make_float2(a0, a1);
    ((float2*)g_ae2)[pos] = make_float2(b0, b1);
}

// ---------------- degree-norm + GEMM + attention-coefficient epilogue -------
__global__ __launch_bounds__(256) void k_gemm(const float* __restrict__ xin_or_null,
                                              int layer,
                                              const float* __restrict__ as_g,
                                              const float* __restrict__ ad_g) {
    __shared__ float sW[FD * 65];
    __shared__ float sX[32 * 65];
    __shared__ float sA[32 * 8];
    __shared__ float sD[32 * 8];

    const float* xin = xin_or_null ? xin_or_null : g_x2;
    const float* dn = (layer == 1) ? g_dn1 : g_dn2;

    int t = threadIdx.x;
    int nb = blockIdx.x * 32;

    for (int i = t; i < FD * KD; i += 256) {
        int o = i >> 6, k = i & 63;
        sW[o * 65 + k] = g_Wq[i];
    }
    for (int i = t; i < 32 * KD; i += 256) {
        int nl = i >> 6, k = i & 63;
        int n = nb + nl;
        sX[nl * 65 + k] = (n < NN) ? xin[n * KD + k] * dn[n] : 0.f;
    }
    __syncthreads();

    int nl = t >> 3;
    int ob = (t & 7) * 16;
    float acc[16];
#pragma unroll
    for (int j = 0; j < 16; j++) acc[j] = 0.f;

    for (int k = 0; k < KD; k++) {
        float xv = sX[nl * 65 + k];
#pragma unroll
        for (int j = 0; j < 16; j++) acc[j] += xv * sW[(ob + j) * 65 + k];
    }

    float ps = 0.f, pd = 0.f;
    int n = nb + nl;
    if (n < NN) {
#pragma unroll
        for (int j = 0; j < 16; j += 4) {
            float4 vv = make_float4(acc[j], acc[j+1], acc[j+2], acc[j+3]);
            *((float4*)&g_h[n * FD + ob + j]) = vv;
        }
#pragma unroll
        for (int j = 0; j < 16; j++) {
            ps += acc[j] * as_g[ob + j];
            pd += acc[j] * ad_g[ob + j];
        }
    }
    sA[nl * 8 + (t & 7)] = ps;
    sD[nl * 8 + (t & 7)] = pd;
    __syncthreads();

    if (t < 64) {
        int nl2 = t >> 1, h = t & 1;
        int base = nl2 * 8 + h * 4;
        float s = sA[base] + sA[base+1] + sA[base+2] + sA[base+3];
        float d = sD[base] + sD[base+1] + sD[base+2] + sD[base+3];
        int n2 = nb + nl2;
        if (n2 < NN) { g_asrc[n2*2+h] = s; g_adst[n2*2+h] = d; }
    }
}

// ---------------- fused softmax + gather + head-mean + bias + maxabs --------
// one warp per destination node; NO atomics on the feature accumulator.
// grid is exactly NN/8 blocks of 8 warps (100000 % 8 == 0), so no early exit.
__global__ __launch_bounds__(256) void k_gather(int layer, const float* __restrict__ bias) {
    const float2* aecsr = (layer == 1) ? (const float2*)g_ae1 : (const float2*)g_ae2;
    int wid  = (blockIdx.x * 256 + threadIdx.x) >> 5;   // dst node
    int lane = threadIdx.x & 31;

    int beg = g_doff[wid];
    int deg = g_doff[wid + 1] - beg;
    float2 ad = ((const float2*)g_adst)[wid];

    // ---- pass 1: softmax denominator ----
    float den0 = 0.f, den1 = 0.f;
    for (int base = 0; base < deg; base += 32) {
        if (base + lane < deg) {
            int s = g_srcs[beg + base + lane];
            float2 as = ((const float2*)g_asrc)[s];
            float2 ae = aecsr[beg + base + lane];
            float x0 = as.x + ad.x + ae.x; x0 = (x0 >= 0.f) ? x0 : 0.2f * x0;
            float x1 = as.y + ad.y + ae.y; x1 = (x1 >= 0.f) ? x1 : 0.2f * x1;
            den0 += __expf(x0);
            den1 += __expf(x1);
        }
    }
#pragma unroll
    for (int o = 16; o; o >>= 1) {
        den0 += __shfl_xor_sync(0xffffffffu, den0, o);
        den1 += __shfl_xor_sync(0xffffffffu, den1, o);
    }
    float inv0 = 1.f / (den0 + 1e-16f);
    float inv1 = 1.f / (den1 + 1e-16f);

    // ---- pass 2: weighted gather-accumulate ----
    float a0 = 0.f, a1 = 0.f, a2 = 0.f, a3 = 0.f;
    for (int base = 0; base < deg; base += 32) {
        int cnt = min(32, deg - base);
        int s = 0; float e0 = 0.f, e1 = 0.f;
        if (lane < cnt) {
            s = g_srcs[beg + base + lane];
            float2 as = ((const float2*)g_asrc)[s];
            float2 ae = aecsr[beg + base + lane];
            float x0 = as.x + ad.x + ae.x; x0 = (x0 >= 0.f) ? x0 : 0.2f * x0;
            float x1 = as.y + ad.y + ae.y; x1 = (x1 >= 0.f) ? x1 : 0.2f * x1;
            e0 = __expf(x0);
            e1 = __expf(x1);
        }
        for (int k = 0; k < cnt; k++) {
            int   sk = __shfl_sync(0xffffffffu, s, k);
            float w0 = __shfl_sync(0xffffffffu, e0, k);
            float w1 = __shfl_sync(0xffffffffu, e1, k);
            float w  = (lane < 16) ? w0 * inv0 : w1 * inv1;
            float4 hv = ((const float4*)g_h)[(size_t)sk * 32 + lane];
            a0 += w * hv.x; a1 += w * hv.y; a2 += w * hv.z; a3 += w * hv.w;
        }
    }

    // combine heads: lane l (<16) += lane l+16  (head1, same channel)
    a0 += __shfl_xor_sync(0xffffffffu, a0, 16);
    a1 += __shfl_xor_sync(0xffffffffu, a1, 16);
    a2 += __shfl_xor_sync(0xffffffffu, a2, 16);
    a3 += __shfl_xor_sync(0xffffffffu, a3, 16);

    float mv = 0.f;
    if (lane < 16) {
        float4 bb = ((const float4*)bias)[lane];
        float4 t = make_float4(a0 * 0.5f + bb.x, a1 * 0.5f + bb.y,
                               a2 * 0.5f + bb.z, a3 * 0.5f + bb.w);
        ((float4*)(g_x2 + (size_t)wid * KD))[lane] = t;
        mv = fmaxf(fmaxf(fabsf(t.x), fabsf(t.y)), fmaxf(fabsf(t.z), fabsf(t.w)));
    }
#pragma unroll
    for (int o = 16; o; o >>= 1) mv = fmaxf(mv, __shfl_xor_sync(0xffffffffu, mv, o));

    __shared__ float sred[8];
    if (lane == 0) sred[threadIdx.x >> 5] = mv;
    __syncthreads();
    if (threadIdx.x < 8) {
        float v = sred[threadIdx.x];
#pragma unroll
        for (int o = 4; o; o >>= 1) v = fmaxf(v, __shfl_xor_sync(0xffu, v, o));
        if (threadIdx.x == 0) atomicMax(&g_imax[0], __float_as_int(v));
    }
}

// ---------------- per-tensor fake-quant of output ---------------------------
__global__ void k_fin_post(float* __restrict__ out, int relu) {
    int i = blockIdx.x * blockDim.x + threadIdx.x;
    if (i >= NN * KD) return;
    float s = fmaxf(__int_as_float(g_imax[0]), 1e-8f) * (1.f / 127.f);
    float q = rintf(g_x2[i] / s);
    q = fminf(fmaxf(q, -128.f), 127.f) * s;
    if (relu) q = fmaxf(q, 0.f);
    if (out) out[i] = q;
    else     g_x2[i] = q;
}

// ---------------- host ------------------------------------------------------
extern "C" void kernel_launch(void* const* d_in, const int* in_sizes, int n_in,
                              void* d_out, int out_size) {
    const float* x    = (const float*)d_in[0];
    const int*   ei   = (const int*)d_in[1];
    const int*   src  = ei;
    const int*   dst  = ei + EE;
    const float* ea   = (const float*)d_in[2];
    const float* a1   = (const float*)d_in[3];
    const float* W1   = (const float*)d_in[4];
    const float* We1  = (const float*)d_in[5];
    const float* as1  = (const float*)d_in[6];
    const float* ad1  = (const float*)d_in[7];
    const float* ae1  = (const float*)d_in[8];
    const float* b1   = (const float*)d_in[9];
    const float* a2   = (const float*)d_in[10];
    const float* W2   = (const float*)d_in[11];
    const float* We2  = (const float*)d_in[12];
    const float* as2  = (const float*)d_in[13];
    const float* ad2  = (const float*)d_in[14];
    const float* ae2  = (const float*)d_in[15];
    const float* b2   = (const float*)d_in[16];
    float* out = (float*)d_out;

    const int TB = 256;
    int gN   = (NN + TB - 1) / TB;
    int gE   = (EE + TB - 1) / TB;
    int gW   = (FD * KD + TB - 1) / TB;
    int gGem = (NN + 31) / 32;
    int gGat = NN / 8;                  // 100000 % 8 == 0 : exact
    int gF   = (NN * KD + TB - 1) / TB;

    // shared precompute (CSR + a_edge for both layers)
    k_zero<<<gN, TB>>>();
    k_deg<<<gE, TB>>>(src, dst);
    k_dnorm<<<gN, TB>>>(a1, a2);
    k_scan<<<1, 1024>>>();
    k_fill<<<gE, TB>>>(src, dst);
    k_vedge<<<1, 256>>>(We1, ae1, We2, ae2);
    k_edgepre<<<gE, TB>>>(ea);

    // ---- layer 1 ----
    k_maxabsW<<<1, 256>>>(W1);
    k_quantW<<<gW, TB>>>(W1);
    k_gemm<<<gGem, 256>>>(x, 1, as1, ad1);
    k_gather<<<gGat, 256>>>(1, b1);
    k_fin_post<<<gF, TB>>>(nullptr, 1);

    // ---- layer 2 ----
    k_maxabsW<<<1, 256>>>(W2);
    k_quantW<<<gW, TB>>>(W2);
    k_gemm<<<gGem, 256>>>(nullptr, 2, as2, ad2);
    k_gather<<<gGat, 256>>>(2, b2);
    k_fin_post<<<gF, TB>>>(out, 0);
}

// round 5
// speedup vs baseline: 1.1062x; 1.1062x over previous
#include <cuda_runtime.h>
#include <math.h>
#include <stdint.h>

#define NN 100000
#define EE 800000
#define FD 128   // H * C
#define KD 64    // input/output dim of each GEMM
#define EDD 32   // edge attr dim
#define HH 2     // heads
#define SCB 98   // ceil(NN / 1024) scan blocks

// ---------------- scratch (device globals) -----------------------------------
__device__ int   g_degi[NN];       // src degree (for degree_norm)
__device__ int   g_dcnt[NN];       // dst degree (for CSR)
__device__ int   g_cur[NN];        // CSR fill cursor
__device__ int   g_doff[NN + 1];   // CSR row offsets
__device__ int   g_part[128];      // scan partials
__device__ int   g_srcs[EE];       // src node id, CSR order
__device__ int   g_epos[EE];       // edge -> CSR slot
__device__ float g_dn1[NN];
__device__ float g_dn2[NN];
__device__ float g_Wq[FD * KD];
__device__ float g_ae1[EE * HH];   // a_edge layer 1, CSR order
__device__ float g_ae2[EE * HH];   // a_edge layer 2, CSR order
__device__ float g_h[NN * FD];     // 51.2 MB
__device__ float g_asrc[NN * HH];
__device__ float g_adst[NN * HH];
__device__ float g_x2[NN * KD];    // 25.6 MB (layer-1 raw output, pre-quant)
__device__ float g_wscale[1];
__device__ int   g_imax[2];        // [0]: layer-1 output max, [1]: layer-2

// ---------------- init / degree ----------------------------------------------
__global__ void k_zero() {
    int i = blockIdx.x * blockDim.x + threadIdx.x;
    if (i < NN) { g_degi[i] = 0; g_dcnt[i] = 0; g_cur[i] = 0; }
}

__global__ void k_deg(const int* __restrict__ src, const int* __restrict__ dst) {
    int e = blockIdx.x * blockDim.x + threadIdx.x;
    if (e < EE) {
        atomicAdd(&g_degi[src[e]], 1);
        atomicAdd(&g_dcnt[dst[e]], 1);
    }
}

__global__ void k_dnorm(const float* __restrict__ a1, const float* __restrict__ a2) {
    int n = blockIdx.x * blockDim.x + threadIdx.x;
    if (n < NN) {
        float d = (float)(g_degi[n] + 1);
        g_dn1[n] = powf(d, -a1[0]);
        g_dn2[n] = powf(d, -a2[0]);
    }
}

// ---------------- multi-block exclusive scan of g_dcnt -> g_doff --------------
__global__ void k_scan1() {       // SCB blocks x 256 threads, 4 elems/thread
    int b = blockIdx.x, t = threadIdx.x;
    int i0 = b * 1024 + t * 4;
    int s = 0;
#pragma unroll
    for (int j = 0; j < 4; j++) { int i = i0 + j; if (i < NN) s += g_dcnt[i]; }
    __shared__ int sm[256];
    sm[t] = s; __syncthreads();
    for (int o = 128; o; o >>= 1) { if (t < o) sm[t] += sm[t + o]; __syncthreads(); }
    if (t == 0) g_part[b] = sm[0];
    if (b == 0 && t == 0) g_doff[NN] = EE;
}

__global__ void k_scan2() {       // 1 block, 128 threads: exclusive scan of partials
    int t = threadIdx.x;
    int v = (t < SCB) ? g_part[t] : 0;
    __shared__ int sm[128];
    sm[t] = v; __syncthreads();
    for (int o = 1; o < 128; o <<= 1) {
        int u = (t >= o) ? sm[t - o] : 0;
        __syncthreads(); sm[t] += u; __syncthreads();
    }
    if (t < SCB) g_part[t] = sm[t] - v;   // exclusive
}

__global__ void k_scan3() {       // SCB blocks: local exclusive scan + offset
    int b = blockIdx.x, t = threadIdx.x;
    int i0 = b * 1024 + t * 4;
    int v[4]; int s = 0;
#pragma unroll
    for (int j = 0; j < 4; j++) {
        int i = i0 + j;
        v[j] = (i < NN) ? g_dcnt[i] : 0;
        s += v[j];
    }
    __shared__ int sm[256];
    sm[t] = s; __syncthreads();
    for (int o = 1; o < 256; o <<= 1) {
        int u = (t >= o) ? sm[t - o] : 0;
        __syncthreads(); sm[t] += u; __syncthreads();
    }
    int run = g_part[b] + sm[t] - s;
#pragma unroll
    for (int j = 0; j < 4; j++) {
        int i = i0 + j;
        if (i < NN) g_doff[i] = run;
        run += v[j];
    }
}

__global__ void k_fill(const int* __restrict__ src, const int* __restrict__ dst) {
    int e = blockIdx.x * blockDim.x + threadIdx.x;
    if (e >= EE) return;
    int d = dst[e];
    int pos = g_doff[d] + atomicAdd(&g_cur[d], 1);
    g_srcs[pos] = src[e];
    g_epos[e] = pos;
}

// ---------------- fake-quant of W -------------------------------------------
__global__ void k_maxabsW(const float* __restrict__ w, int slot) {
    __shared__ float sm[256];
    float m = 0.f;
    for (int i = threadIdx.x; i < FD * KD; i += 256) m = fmaxf(m, fabsf(w[i]));
    sm[threadIdx.x] = m;
    __syncthreads();
    for (int s = 128; s > 0; s >>= 1) {
        if (threadIdx.x < s) sm[threadIdx.x] = fmaxf(sm[threadIdx.x], sm[threadIdx.x + s]);
        __syncthreads();
    }
    if (threadIdx.x == 0) {
        g_wscale[0] = fmaxf(sm[0], 1e-8f) / 127.0f;
        g_imax[slot] = 0;              // reset output-quant max for this layer
    }
}

__global__ void k_quantW(const float* __restrict__ w) {
    int i = blockIdx.x * blockDim.x + threadIdx.x;
    if (i < FD * KD) {
        float s = g_wscale[0];
        float q = rintf(w[i] / s);
        q = fminf(fmaxf(q, -128.f), 127.f);
        g_Wq[i] = q * s;
    }
}

// one pass over edge_attr computing a_edge for BOTH layers, CSR order.
// v vectors (64 floats per layer) recomputed per block (cheap, We stays in L2).
__global__ __launch_bounds__(256) void k_edgepre(
        const float* __restrict__ ea,
        const float* __restrict__ We1, const float* __restrict__ ae1,
        const float* __restrict__ We2, const float* __restrict__ ae2) {
    __shared__ float r1[64][4];
    __shared__ float r2[64][4];
    __shared__ float sv1[HH * EDD];
    __shared__ float sv2[HH * EDD];
    {
        int t = threadIdx.x;
        int i = t >> 2, j = t & 3;
        int h = i / EDD, d = i % EDD;
        float s1 = 0.f, s2 = 0.f;
        for (int c = j * 16; c < j * 16 + 16; c++) {
            s1 += ae1[h * 64 + c] * We1[(h * 64 + c) * EDD + d];
            s2 += ae2[h * 64 + c] * We2[(h * 64 + c) * EDD + d];
        }
        r1[i][j] = s1; r2[i][j] = s2;
        __syncthreads();
        if (j == 0) {
            sv1[i] = r1[i][0] + r1[i][1] + r1[i][2] + r1[i][3];
            sv2[i] = r2[i][0] + r2[i][1] + r2[i][2] + r2[i][3];
        }
        __syncthreads();
    }
    int e = blockIdx.x * blockDim.x + threadIdx.x;
    if (e >= EE) return;
    const float4* p = (const float4*)(ea + (size_t)e * EDD);
    float a0 = 0.f, a1 = 0.f, b0 = 0.f, b1 = 0.f;
#pragma unroll
    for (int i = 0; i < 8; i++) {
        float4 q = p[i];
        a0 += q.x * sv1[i*4] + q.y * sv1[i*4+1] + q.z * sv1[i*4+2] + q.w * sv1[i*4+3];
        a1 += q.x * sv1[32+i*4] + q.y * sv1[32+i*4+1] + q.z * sv1[32+i*4+2] + q.w * sv1[32+i*4+3];
        b0 += q.x * sv2[i*4] + q.y * sv2[i*4+1] + q.z * sv2[i*4+2] + q.w * sv2[i*4+3];
        b1 += q.x * sv2[32+i*4] + q.y * sv2[32+i*4+1] + q.z * sv2[32+i*4+2] + q.w * sv2[32+i*4+3];
    }
    int pos = g_epos[e];
    ((float2*)g_ae1)[pos] = make_float2(a0, a1);
    ((float2*)g_ae2)[pos] = make_float2(b0, b1);
}

// ---------------- degree-norm (+opt fq/relu) + GEMM + attention epilogue ----
__global__ __launch_bounds__(256) void k_gemm(const float* __restrict__ xin_or_null,
                                              int layer,
                                              const float* __restrict__ as_g,
                                              const float* __restrict__ ad_g) {
    __shared__ float sW[FD * 65];
    __shared__ float sX[32 * 65];
    __shared__ float sA[32 * 8];
    __shared__ float sD[32 * 8];

    const float* xin = xin_or_null ? xin_or_null : g_x2;
    const float* dn = (layer == 1) ? g_dn1 : g_dn2;
    // layer 2 input = fake_quant(relu applied after) of raw g_x2 (layer-1 output)
    float qs = 0.f;
    if (layer == 2) qs = fmaxf(__int_as_float(g_imax[0]), 1e-8f) * (1.f / 127.f);

    int t = threadIdx.x;
    int nb = blockIdx.x * 32;

    for (int i = t; i < FD * KD; i += 256) {
        int o = i >> 6, k = i & 63;
        sW[o * 65 + k] = g_Wq[i];
    }
    for (int i = t; i < 32 * KD; i += 256) {
        int nl = i >> 6, k = i & 63;
        int n = nb + nl;
        float v = 0.f;
        if (n < NN) {
            v = xin[n * KD + k];
            if (layer == 2) {     // fused fake-quant + relu of layer-1 output
                float q = rintf(v / qs);
                q = fminf(fmaxf(q, -128.f), 127.f) * qs;
                v = fmaxf(q, 0.f);
            }
            v *= dn[n];
        }
        sX[nl * 65 + k] = v;
    }
    __syncthreads();

    int nl = t >> 3;
    int ob = (t & 7) * 16;
    float acc[16];
#pragma unroll
    for (int j = 0; j < 16; j++) acc[j] = 0.f;

    for (int k = 0; k < KD; k++) {
        float xv = sX[nl * 65 + k];
#pragma unroll
        for (int j = 0; j < 16; j++) acc[j] += xv * sW[(ob + j) * 65 + k];
    }

    float ps = 0.f, pd = 0.f;
    int n = nb + nl;
    if (n < NN) {
#pragma unroll
        for (int j = 0; j < 16; j += 4) {
            float4 vv = make_float4(acc[j], acc[j+1], acc[j+2], acc[j+3]);
            *((float4*)&g_h[n * FD + ob + j]) = vv;
        }
#pragma unroll
        for (int j = 0; j < 16; j++) {
            ps += acc[j] * as_g[ob + j];
            pd += acc[j] * ad_g[ob + j];
        }
    }
    sA[nl * 8 + (t & 7)] = ps;
    sD[nl * 8 + (t & 7)] = pd;
    __syncthreads();

    if (t < 64) {
        int nl2 = t >> 1, h = t & 1;
        int base = nl2 * 8 + h * 4;
        float s = sA[base] + sA[base+1] + sA[base+2] + sA[base+3];
        float d = sD[base] + sD[base+1] + sD[base+2] + sD[base+3];
        int n2 = nb + nl2;
        if (n2 < NN) { g_asrc[n2*2+h] = s; g_adst[n2*2+h] = d; }
    }
}

// ---------------- fused SINGLE-PASS softmax+gather+head-mean+bias+maxabs ----
// out = (sum_i e_i * h_i) / (sum_i e_i): accumulate numerator unnormalized and
// denominator simultaneously; divide once at the end. One warp per dst node.
__global__ __launch_bounds__(256) void k_gather(int layer, const float* __restrict__ bias) {
    const float2* aecsr = (layer == 1) ? (const float2*)g_ae1 : (const float2*)g_ae2;
    int wid  = (blockIdx.x * 256 + threadIdx.x) >> 5;   // dst node
    int lane = threadIdx.x & 31;
    int warp = threadIdx.x >> 5;

    __shared__ int   sm_s [8][32];
    __shared__ float sm_e0[8][32];
    __shared__ float sm_e1[8][32];

    int beg = g_doff[wid];
    int deg = g_doff[wid + 1] - beg;
    float2 ad = ((const float2*)g_adst)[wid];

    float den0 = 0.f, den1 = 0.f;
    float a0 = 0.f, a1 = 0.f, a2 = 0.f, a3 = 0.f;

    for (int base = 0; base < deg; base += 32) {
        int cnt = min(32, deg - base);
        int s = 0; float e0 = 0.f, e1 = 0.f;
        if (lane < cnt) {
            s = g_srcs[beg + base + lane];
            float2 as = ((const float2*)g_asrc)[s];
            float2 ae = aecsr[beg + base + lane];
            float x0 = as.x + ad.x + ae.x; x0 = (x0 >= 0.f) ? x0 : 0.2f * x0;
            float x1 = as.y + ad.y + ae.y; x1 = (x1 >= 0.f) ? x1 : 0.2f * x1;
            e0 = __expf(x0);
            e1 = __expf(x1);
        }
        den0 += e0; den1 += e1;
        sm_s [warp][lane] = s;
        sm_e0[warp][lane] = e0;
        sm_e1[warp][lane] = e1;
        __syncwarp();
        for (int k = 0; k < cnt; k++) {
            int   sk = sm_s [warp][k];
            float w  = (lane < 16) ? sm_e0[warp][k] : sm_e1[warp][k];
            float4 hv = ((const float4*)g_h)[(size_t)sk * 32 + lane];
            a0 += w * hv.x; a1 += w * hv.y; a2 += w * hv.z; a3 += w * hv.w;
        }
        __syncwarp();
    }

#pragma unroll
    for (int o = 16; o; o >>= 1) {
        den0 += __shfl_xor_sync(0xffffffffu, den0, o);
        den1 += __shfl_xor_sync(0xffffffffu, den1, o);
    }
    float inv = (lane < 16) ? 1.f / (den0 + 1e-16f) : 1.f / (den1 + 1e-16f);
    a0 *= inv; a1 *= inv; a2 *= inv; a3 *= inv;

    // combine heads: lane l (<16, head0) += lane l+16 (head1, same channel)
    a0 += __shfl_xor_sync(0xffffffffu, a0, 16);
    a1 += __shfl_xor_sync(0xffffffffu, a1, 16);
    a2 += __shfl_xor_sync(0xffffffffu, a2, 16);
    a3 += __shfl_xor_sync(0xffffffffu, a3, 16);

    float mv = 0.f;
    if (lane < 16) {
        float4 bb = ((const float4*)bias)[lane];
        float4 t = make_float4(a0 * 0.5f + bb.x, a1 * 0.5f + bb.y,
                               a2 * 0.5f + bb.z, a3 * 0.5f + bb.w);
        ((float4*)(g_x2 + (size_t)wid * KD))[lane] = t;
        mv = fmaxf(fmaxf(fabsf(t.x), fabsf(t.y)), fmaxf(fabsf(t.z), fabsf(t.w)));
    }
#pragma unroll
    for (int o = 16; o; o >>= 1) mv = fmaxf(mv, __shfl_xor_sync(0xffffffffu, mv, o));

    __shared__ float sred[8];
    if (lane == 0) sred[warp] = mv;
    __syncthreads();
    if (threadIdx.x < 8) {
        float v = sred[threadIdx.x];
#pragma unroll
        for (int o = 4; o; o >>= 1) v = fmaxf(v, __shfl_xor_sync(0xffu, v, o));
        if (threadIdx.x == 0) atomicMax(&g_imax[layer - 1], __float_as_int(v));
    }
}

// ---------------- final per-tensor fake-quant (layer 2 output only) ---------
__global__ void k_fin_post(float* __restrict__ out) {
    int i = blockIdx.x * blockDim.x + threadIdx.x;
    if (i >= NN * KD) return;
    float s = fmaxf(__int_as_float(g_imax[1]), 1e-8f) * (1.f / 127.f);
    float q = rintf(g_x2[i] / s);
    q = fminf(fmaxf(q, -128.f), 127.f) * s;
    out[i] = q;
}

// ---------------- host ------------------------------------------------------
extern "C" void kernel_launch(void* const* d_in, const int* in_sizes, int n_in,
                              void* d_out, int out_size) {
    const float* x    = (const float*)d_in[0];
    const int*   ei   = (const int*)d_in[1];
    const int*   src  = ei;
    const int*   dst  = ei + EE;
    const float* ea   = (const float*)d_in[2];
    const float* a1   = (const float*)d_in[3];
    const float* W1   = (const float*)d_in[4];
    const float* We1  = (const float*)d_in[5];
    const float* as1  = (const float*)d_in[6];
    const float* ad1  = (const float*)d_in[7];
    const float* ae1  = (const float*)d_in[8];
    const float* b1   = (const float*)d_in[9];
    const float* a2   = (const float*)d_in[10];
    const float* W2   = (const float*)d_in[11];
    const float* We2  = (const float*)d_in[12];
    const float* as2  = (const float*)d_in[13];
    const float* ad2  = (const float*)d_in[14];
    const float* ae2  = (const float*)d_in[15];
    const float* b2   = (const float*)d_in[16];
    float* out = (float*)d_out;

    const int TB = 256;
    int gN   = (NN + TB - 1) / TB;
    int gE   = (EE + TB - 1) / TB;
    int gW   = (FD * KD + TB - 1) / TB;
    int gGem = (NN + 31) / 32;
    int gGat = NN / 8;
    int gF   = (NN * KD + TB - 1) / TB;

    // shared precompute (CSR + a_edge for both layers)
    k_zero<<<gN, TB>>>();
    k_deg<<<gE, TB>>>(src, dst);
    k_dnorm<<<gN, TB>>>(a1, a2);
    k_scan1<<<SCB, 256>>>();
    k_scan2<<<1, 128>>>();
    k_scan3<<<SCB, 256>>>();
    k_fill<<<gE, TB>>>(src, dst);
    k_edgepre<<<gE, TB>>>(ea, We1, ae1, We2, ae2);

    // ---- layer 1 ----
    k_maxabsW<<<1, 256>>>(W1, 0);
    k_quantW<<<gW, TB>>>(W1);
    k_gemm<<<gGem, 256>>>(x, 1, as1, ad1);
    k_gather<<<gGat, 256>>>(1, b1);

    // ---- layer 2 (input fq+relu fused into gemm load) ----
    k_maxabsW<<<1, 256>>>(W2, 1);
    k_quantW<<<gW, TB>>>(W2);
    k_gemm<<<gGem, 256>>>(nullptr, 2, as2, ad2);
    k_gather<<<gGat, 256>>>(2, b2);
    k_fin_post<<<gF, TB>>>(out);
}

// round 6
// speedup vs baseline: 2.8180x; 2.5474x over previous
#include <cuda_runtime.h>
#include <math.h>
#include <stdint.h>

#define NN 100000
#define EE 800000
#define FD 128   // H * C
#define KD 64    // input/output dim of each GEMM
#define EDD 32   // edge attr dim
#define HH 2     // heads
#define SCB 98   // ceil(NN / 1024) scan blocks

// ---------------- scratch (device globals) -----------------------------------
__device__ int   g_degi[NN];       // src degree (for degree_norm)
__device__ int   g_dcnt[NN];       // dst degree (for CSR)
__device__ int   g_cur[NN];        // CSR fill cursor
__device__ int   g_doff[NN + 1];   // CSR row offsets
__device__ int   g_part[128];      // scan partials
__device__ int   g_epos[EE];       // edge -> CSR slot
__device__ float g_dn1[NN];
__device__ float g_dn2[NN];
__device__ float g_Wq[FD * KD];
__device__ float4 g_ed1[EE];       // (src, ae0, ae1, -) layer 1, CSR order
__device__ float4 g_ed2[EE];       // (src, ae0, ae1, -) layer 2, CSR order
__device__ float g_h[NN * FD];     // 51.2 MB
__device__ float g_asrc[NN * HH];
__device__ float g_adst[NN * HH];
__device__ float g_x2[NN * KD];    // 25.6 MB (layer-1 raw output, pre-quant)
__device__ float g_wscale[1];
__device__ int   g_imax[2];        // [0]: layer-1 output max, [1]: layer-2

// ---------------- init / degree ----------------------------------------------
__global__ void k_zero() {
    int i = blockIdx.x * blockDim.x + threadIdx.x;
    if (i < NN) { g_degi[i] = 0; g_dcnt[i] = 0; g_cur[i] = 0; }
}

__global__ void k_deg(const int* __restrict__ src, const int* __restrict__ dst) {
    int e = blockIdx.x * blockDim.x + threadIdx.x;
    if (e < EE) {
        atomicAdd(&g_degi[src[e]], 1);
        atomicAdd(&g_dcnt[dst[e]], 1);
    }
}

// fused: degree-norm for all nodes (blocks 0..gN-1) + W1 fake-quant (last block)
__global__ void k_prep(const float* __restrict__ a1, const float* __restrict__ a2,
                       const float* __restrict__ w, int gN) {
    if ((int)blockIdx.x < gN) {
        int n = blockIdx.x * blockDim.x + threadIdx.x;
        if (n < NN) {
            float d = (float)(g_degi[n] + 1);
            g_dn1[n] = powf(d, -a1[0]);
            g_dn2[n] = powf(d, -a2[0]);
        }
        return;
    }
    // weight fake-quant block
    __shared__ float sm[256];
    float m = 0.f;
    for (int i = threadIdx.x; i < FD * KD; i += 256) m = fmaxf(m, fabsf(w[i]));
    sm[threadIdx.x] = m;
    __syncthreads();
    for (int s = 128; s > 0; s >>= 1) {
        if (threadIdx.x < s) sm[threadIdx.x] = fmaxf(sm[threadIdx.x], sm[threadIdx.x + s]);
        __syncthreads();
    }
    __shared__ float ssc;
    if (threadIdx.x == 0) {
        ssc = fmaxf(sm[0], 1e-8f) / 127.0f;
        g_wscale[0] = ssc;
        g_imax[0] = 0; g_imax[1] = 0;
    }
    __syncthreads();
    float s = ssc;
    for (int i = threadIdx.x; i < FD * KD; i += 256) {
        float q = rintf(w[i] / s);
        q = fminf(fmaxf(q, -128.f), 127.f);
        g_Wq[i] = q * s;
    }
}

// ---------------- multi-block exclusive scan of g_dcnt -> g_doff --------------
__global__ void k_scan1() {
    int b = blockIdx.x, t = threadIdx.x;
    int i0 = b * 1024 + t * 4;
    int s = 0;
#pragma unroll
    for (int j = 0; j < 4; j++) { int i = i0 + j; if (i < NN) s += g_dcnt[i]; }
    __shared__ int sm[256];
    sm[t] = s; __syncthreads();
    for (int o = 128; o; o >>= 1) { if (t < o) sm[t] += sm[t + o]; __syncthreads(); }
    if (t == 0) g_part[b] = sm[0];
    if (b == 0 && t == 0) g_doff[NN] = EE;
}

__global__ void k_scan2() {
    int t = threadIdx.x;
    int v = (t < SCB) ? g_part[t] : 0;
    __shared__ int sm[128];
    sm[t] = v; __syncthreads();
    for (int o = 1; o < 128; o <<= 1) {
        int u = (t >= o) ? sm[t - o] : 0;
        __syncthreads(); sm[t] += u; __syncthreads();
    }
    if (t < SCB) g_part[t] = sm[t] - v;
}

__global__ void k_scan3() {
    int b = blockIdx.x, t = threadIdx.x;
    int i0 = b * 1024 + t * 4;
    int v[4]; int s = 0;
#pragma unroll
    for (int j = 0; j < 4; j++) {
        int i = i0 + j;
        v[j] = (i < NN) ? g_dcnt[i] : 0;
        s += v[j];
    }
    __shared__ int sm[256];
    sm[t] = s; __syncthreads();
    for (int o = 1; o < 256; o <<= 1) {
        int u = (t >= o) ? sm[t - o] : 0;
        __syncthreads(); sm[t] += u; __syncthreads();
    }
    int run = g_part[b] + sm[t] - s;
#pragma unroll
    for (int j = 0; j < 4; j++) {
        int i = i0 + j;
        if (i < NN) g_doff[i] = run;
        run += v[j];
    }
}

__global__ void k_fill(const int* __restrict__ dst) {
    int e = blockIdx.x * blockDim.x + threadIdx.x;
    if (e >= EE) return;
    int d = dst[e];
    g_epos[e] = g_doff[d] + atomicAdd(&g_cur[d], 1);
}

// ---------------- fake-quant of W (layer 2) ----------------------------------
__global__ void k_maxabsW(const float* __restrict__ w, int slot) {
    __shared__ float sm[256];
    float m = 0.f;
    for (int i = threadIdx.x; i < FD * KD; i += 256) m = fmaxf(m, fabsf(w[i]));
    sm[threadIdx.x] = m;
    __syncthreads();
    for (int s = 128; s > 0; s >>= 1) {
        if (threadIdx.x < s) sm[threadIdx.x] = fmaxf(sm[threadIdx.x], sm[threadIdx.x + s]);
        __syncthreads();
    }
    if (threadIdx.x == 0) {
        g_wscale[0] = fmaxf(sm[0], 1e-8f) / 127.0f;
        g_imax[slot] = 0;
    }
}

__global__ void k_quantW(const float* __restrict__ w) {
    int i = blockIdx.x * blockDim.x + threadIdx.x;
    if (i < FD * KD) {
        float s = g_wscale[0];
        float q = rintf(w[i] / s);
        q = fminf(fmaxf(q, -128.f), 127.f);
        g_Wq[i] = q * s;
    }
}

// one pass over edge_attr: a_edge for BOTH layers, packed with src, CSR order.
__global__ __launch_bounds__(256) void k_edgepre(
        const float* __restrict__ ea, const int* __restrict__ src,
        const float* __restrict__ We1, const float* __restrict__ ae1,
        const float* __restrict__ We2, const float* __restrict__ ae2) {
    __shared__ float r1[64][4];
    __shared__ float r2[64][4];
    __shared__ float sv1[HH * EDD];
    __shared__ float sv2[HH * EDD];
    {
        int t = threadIdx.x;
        int i = t >> 2, j = t & 3;
        int h = i / EDD, d = i % EDD;
        float s1 = 0.f, s2 = 0.f;
        for (int c = j * 16; c < j * 16 + 16; c++) {
            s1 += ae1[h * 64 + c] * We1[(h * 64 + c) * EDD + d];
            s2 += ae2[h * 64 + c] * We2[(h * 64 + c) * EDD + d];
        }
        r1[i][j] = s1; r2[i][j] = s2;
        __syncthreads();
        if (j == 0) {
            sv1[i] = r1[i][0] + r1[i][1] + r1[i][2] + r1[i][3];
            sv2[i] = r2[i][0] + r2[i][1] + r2[i][2] + r2[i][3];
        }
        __syncthreads();
    }
    int e = blockIdx.x * blockDim.x + threadIdx.x;
    if (e >= EE) return;
    const float4* p = (const float4*)(ea + (size_t)e * EDD);
    float a0 = 0.f, a1 = 0.f, b0 = 0.f, b1 = 0.f;
#pragma unroll
    for (int i = 0; i < 8; i++) {
        float4 q = p[i];
        a0 += q.x * sv1[i*4] + q.y * sv1[i*4+1] + q.z * sv1[i*4+2] + q.w * sv1[i*4+3];
        a1 += q.x * sv1[32+i*4] + q.y * sv1[32+i*4+1] + q.z * sv1[32+i*4+2] + q.w * sv1[32+i*4+3];
        b0 += q.x * sv2[i*4] + q.y * sv2[i*4+1] + q.z * sv2[i*4+2] + q.w * sv2[i*4+3];
        b1 += q.x * sv2[32+i*4] + q.y * sv2[32+i*4+1] + q.z * sv2[32+i*4+2] + q.w * sv2[32+i*4+3];
    }
    int pos = g_epos[e];
    float sf = __int_as_float(src[e]);
    g_ed1[pos] = make_float4(sf, a0, a1, 0.f);
    g_ed2[pos] = make_float4(sf, b0, b1, 0.f);
}

// ---------------- degree-norm (+fq/relu) + GEMM + attention epilogue --------
// bank-conflict-free: W transposed [k][o] (broadcast LDS.128), X [node][k]
// (65-stride -> 32 distinct banks). warp = 16 contiguous outputs, lane = node.
__global__ __launch_bounds__(256) void k_gemm(const float* __restrict__ xin_or_null,
                                              int layer,
                                              const float* __restrict__ as_g,
                                              const float* __restrict__ ad_g) {
    __shared__ float sWt[KD * 132];     // [k][o], padded stride 132
    __shared__ float sX[32 * 65];       // [node][k]
    __shared__ float sAp[8][33];
    __shared__ float sDp[8][33];

    const float* xin = xin_or_null ? xin_or_null : g_x2;
    const float* dn = (layer == 1) ? g_dn1 : g_dn2;
    float qs = 0.f;
    if (layer == 2) qs = fmaxf(__int_as_float(g_imax[0]), 1e-8f) * (1.f / 127.f);

    int t = threadIdx.x;
    int nb = blockIdx.x * 32;

    for (int i = t; i < FD * KD; i += 256) {
        int o = i >> 6, k = i & 63;
        sWt[k * 132 + o] = g_Wq[i];
    }
    for (int i = t; i < 32 * KD; i += 256) {
        int nl = i >> 6, k = i & 63;
        int n = nb + nl;
        float v = 0.f;
        if (n < NN) {
            v = xin[n * KD + k];
            if (layer == 2) {     // fused fake-quant + relu of layer-1 output
                float q = rintf(v / qs);
                q = fminf(fmaxf(q, -128.f), 127.f) * qs;
                v = fmaxf(q, 0.f);
            }
            v *= dn[n];
        }
        sX[nl * 65 + k] = v;
    }
    __syncthreads();

    int w = t >> 5, lane = t & 31;
    int ob = w * 16;
    float acc[16];
#pragma unroll
    for (int j = 0; j < 16; j++) acc[j] = 0.f;

#pragma unroll 4
    for (int k = 0; k < KD; k++) {
        float xv = sX[lane * 65 + k];
        const float4* wr = (const float4*)&sWt[k * 132 + ob];
        float4 w0 = wr[0], w1 = wr[1], w2 = wr[2], w3 = wr[3];
        acc[0]  += xv * w0.x; acc[1]  += xv * w0.y; acc[2]  += xv * w0.z; acc[3]  += xv * w0.w;
        acc[4]  += xv * w1.x; acc[5]  += xv * w1.y; acc[6]  += xv * w1.z; acc[7]  += xv * w1.w;
        acc[8]  += xv * w2.x; acc[9]  += xv * w2.y; acc[10] += xv * w2.z; acc[11] += xv * w2.w;
        acc[12] += xv * w3.x; acc[13] += xv * w3.y; acc[14] += xv * w3.z; acc[15] += xv * w3.w;
    }

    int n = nb + lane;
    float ps = 0.f, pd = 0.f;
    if (n < NN) {
        float4* hp = (float4*)&g_h[(size_t)n * FD + ob];
        hp[0] = make_float4(acc[0],  acc[1],  acc[2],  acc[3]);
        hp[1] = make_float4(acc[4],  acc[5],  acc[6],  acc[7]);
        hp[2] = make_float4(acc[8],  acc[9],  acc[10], acc[11]);
        hp[3] = make_float4(acc[12], acc[13], acc[14], acc[15]);
#pragma unroll
        for (int j = 0; j < 16; j++) {
            ps += acc[j] * as_g[ob + j];
            pd += acc[j] * ad_g[ob + j];
        }
    }
    sAp[w][lane] = ps;
    sDp[w][lane] = pd;
    __syncthreads();

    if (t < 64) {
        int nl = t & 31, h = t >> 5;
        int wb = h * 4;
        float s = sAp[wb][nl] + sAp[wb+1][nl] + sAp[wb+2][nl] + sAp[wb+3][nl];
        float d = sDp[wb][nl] + sDp[wb+1][nl] + sDp[wb+2][nl] + sDp[wb+3][nl];
        int n2 = nb + nl;
        if (n2 < NN) { g_asrc[n2*2+h] = s; g_adst[n2*2+h] = d; }
    }
}

// ---------------- fused SINGLE-PASS softmax+gather+head-mean+bias+maxabs ----
__global__ __launch_bounds__(256) void k_gather(int layer, const float* __restrict__ bias) {
    const float4* ed = (layer == 1) ? g_ed1 : g_ed2;
    int wid  = (blockIdx.x * 256 + threadIdx.x) >> 5;   // dst node
    int lane = threadIdx.x & 31;
    int warp = threadIdx.x >> 5;

    __shared__ int   sm_s [8][32];
    __shared__ float sm_e0[8][32];
    __shared__ float sm_e1[8][32];

    int beg = g_doff[wid];
    int deg = g_doff[wid + 1] - beg;
    float2 ad = ((const float2*)g_adst)[wid];

    float den0 = 0.f, den1 = 0.f;
    float a0 = 0.f, a1 = 0.f, a2 = 0.f, a3 = 0.f;

    for (int base = 0; base < deg; base += 32) {
        int cnt = min(32, deg - base);
        int s = 0; float e0 = 0.f, e1 = 0.f;
        if (lane < cnt) {
            float4 er = ed[beg + base + lane];
            s = __float_as_int(er.x);
            float2 as = ((const float2*)g_asrc)[s];
            float x0 = as.x + ad.x + er.y; x0 = (x0 >= 0.f) ? x0 : 0.2f * x0;
            float x1 = as.y + ad.y + er.z; x1 = (x1 >= 0.f) ? x1 : 0.2f * x1;
            e0 = __expf(x0);
            e1 = __expf(x1);
        }
        den0 += e0; den1 += e1;
        sm_s [warp][lane] = s;
        sm_e0[warp][lane] = e0;
        sm_e1[warp][lane] = e1;
        __syncwarp();
        for (int k = 0; k < cnt; k++) {
            int   sk = sm_s [warp][k];
            float w  = (lane < 16) ? sm_e0[warp][k] : sm_e1[warp][k];
            float4 hv = ((const float4*)g_h)[(size_t)sk * 32 + lane];
            a0 += w * hv.x; a1 += w * hv.y; a2 += w * hv.z; a3 += w * hv.w;
        }
        __syncwarp();
    }

#pragma unroll
    for (int o = 16; o; o >>= 1) {
        den0 += __shfl_xor_sync(0xffffffffu, den0, o);
        den1 += __shfl_xor_sync(0xffffffffu, den1, o);
    }
    float inv = (lane < 16) ? 1.f / (den0 + 1e-16f) : 1.f / (den1 + 1e-16f);
    a0 *= inv; a1 *= inv; a2 *= inv; a3 *= inv;

    a0 += __shfl_xor_sync(0xffffffffu, a0, 16);
    a1 += __shfl_xor_sync(0xffffffffu, a1, 16);
    a2 += __shfl_xor_sync(0xffffffffu, a2, 16);
    a3 += __shfl_xor_sync(0xffffffffu, a3, 16);

    float mv = 0.f;
    if (lane < 16) {
        float4 bb = ((const float4*)bias)[lane];
        float4 t = make_float4(a0 * 0.5f + bb.x, a1 * 0.5f + bb.y,
                               a2 * 0.5f + bb.z, a3 * 0.5f + bb.w);
        ((float4*)(g_x2 + (size_t)wid * KD))[lane] = t;
        mv = fmaxf(fmaxf(fabsf(t.x), fabsf(t.y)), fmaxf(fabsf(t.z), fabsf(t.w)));
    }
#pragma unroll
    for (int o = 16; o; o >>= 1) mv = fmaxf(mv, __shfl_xor_sync(0xffffffffu, mv, o));

    __shared__ float sred[8];
    if (lane == 0) sred[warp] = mv;
    __syncthreads();
    if (threadIdx.x < 8) {
        float v = sred[threadIdx.x];
#pragma unroll
        for (int o = 4; o; o >>= 1) v = fmaxf(v, __shfl_xor_sync(0xffu, v, o));
        if (threadIdx.x == 0) atomicMax(&g_imax[layer - 1], __float_as_int(v));
    }
}

// ---------------- final per-tensor fake-quant (layer 2 output only) ---------
__global__ void k_fin_post(float* __restrict__ out) {
    int i = blockIdx.x * blockDim.x + threadIdx.x;
    if (i >= NN * KD) return;
    float s = fmaxf(__int_as_float(g_imax[1]), 1e-8f) * (1.f / 127.f);
    float q = rintf(g_x2[i] / s);
    q = fminf(fmaxf(q, -128.f), 127.f) * s;
    out[i] = q;
}

// ---------------- host ------------------------------------------------------
extern "C" void kernel_launch(void* const* d_in, const int* in_sizes, int n_in,
                              void* d_out, int out_size) {
    const float* x    = (const float*)d_in[0];
    const int*   ei   = (const int*)d_in[1];
    const int*   src  = ei;
    const int*   dst  = ei + EE;
    const float* ea   = (const float*)d_in[2];
    const float* a1   = (const float*)d_in[3];
    const float* W1   = (const float*)d_in[4];
    const float* We1  = (const float*)d_in[5];
    const float* as1  = (const float*)d_in[6];
    const float* ad1  = (const float*)d_in[7];
    const float* ae1  = (const float*)d_in[8];
    const float* b1   = (const float*)d_in[9];
    const float* a2   = (const float*)d_in[10];
    const float* W2   = (const float*)d_in[11];
    const float* We2  = (const float*)d_in[12];
    const float* as2  = (const float*)d_in[13];
    const float* ad2  = (const float*)d_in[14];
    const float* ae2  = (const float*)d_in[15];
    const float* b2   = (const float*)d_in[16];
    float* out = (float*)d_out;

    const int TB = 256;
    int gN   = (NN + TB - 1) / TB;
    int gE   = (EE + TB - 1) / TB;
    int gW   = (FD * KD + TB - 1) / TB;
    int gGem = (NN + 31) / 32;
    int gGat = NN / 8;
    int gF   = (NN * KD + TB - 1) / TB;

    k_zero<<<gN, TB>>>();                               // 1
    k_deg<<<gE, TB>>>(src, dst);                        // 2
    k_prep<<<gN + 1, TB>>>(a1, a2, W1, gN);             // 3: dnorm + W1 quant
    k_gemm<<<gGem, 256>>>(x, 1, as1, ad1);              // 4  <- profile slot

    k_scan1<<<SCB, 256>>>();                            // 5
    k_scan2<<<1, 128>>>();                              // 6
    k_scan3<<<SCB, 256>>>();                            // 7
    k_fill<<<gE, TB>>>(dst);                            // 8
    k_edgepre<<<gE, TB>>>(ea, src, We1, ae1, We2, ae2); // 9
    k_gather<<<gGat, 256>>>(1, b1);                     // 10

    k_maxabsW<<<1, 256>>>(W2, 1);                       // 11
    k_quantW<<<gW, TB>>>(W2);                           // 12
    k_gemm<<<gGem, 256>>>(nullptr, 2, as2, ad2);        // 13
    k_gather<<<gGat, 256>>>(2, b2);                     // 14
    k_fin_post<<<gF, TB>>>(out);                        // 15
}